// round 3
// baseline (speedup 1.0000x reference)
#include <cuda_runtime.h>
#include <cstdint>

// ---------------------------------------------------------------------------
// Decode layer: B=4, LT=LS=1024, D=1024, H=16, HD=64, F=4096
// Output layout (flattened reference leaves):
//   [0)          mlp_x  [B,LT,D]
//   [seg)        k_s    [B,H,LT,HD]
//   [2*seg)      v_s    [B,H,LT,HD]
//   [3*seg)      k_c    [B,H,LS,HD]
//   [4*seg)      v_c    [B,H,LS,HD]       seg = 4*1024*1024
// ---------------------------------------------------------------------------

#define NB 4
#define NL 1024
#define ND 1024
#define NH 16
#define NHD 64
#define NF 4096
#define NROWS (NB * NL)          // 4096
#define SEG   ((size_t)NB * NL * ND)   // 4,194,304

// ---------------- scratch (device globals; no allocations allowed) ---------
__device__ float g_h [NROWS * ND];       // normed activations        16 MB
__device__ float g_q [NB * NH * NL * NHD]; // Q in head layout        16 MB
__device__ float g_o [NROWS * ND];       // attn output [B,L,D]       16 MB
__device__ float g_x1[NROWS * ND];       // attn_x residual stream    16 MB
__device__ float g_x2[NROWS * ND];       // cross_x residual stream   16 MB
__device__ float g_s [(size_t)NB * NH * NL * NL]; // scores          256 MB
__device__ float g_t [NROWS * NF];       // FFN hidden                64 MB
__device__ float g_kv[4 * NROWS * NHD * NH / NH * 1]; // fallback (unused if out has 5 segs)
// NOTE: g_kv sized below properly:
__device__ float g_kv_full[4 * (size_t)NB * NH * NL * NHD]; // 64 MB fallback

// ---------------------------------------------------------------------------
// RMSNorm: one block per row of 1024, 256 threads (float4 each)
// ---------------------------------------------------------------------------
__global__ __launch_bounds__(256) void rmsnorm_kernel(
    const float* __restrict__ x, const float* __restrict__ g, float* __restrict__ o)
{
    __shared__ float red[8];
    const size_t base = (size_t)blockIdx.x * ND;
    const int t = threadIdx.x;
    float4 v = ((const float4*)(x + base))[t];
    float ss = v.x*v.x + v.y*v.y + v.z*v.z + v.w*v.w;
    #pragma unroll
    for (int off = 16; off; off >>= 1) ss += __shfl_xor_sync(0xFFFFFFFFu, ss, off);
    if ((t & 31) == 0) red[t >> 5] = ss;
    __syncthreads();
    if (t < 32) {
        float s = (t < 8) ? red[t] : 0.0f;
        #pragma unroll
        for (int off = 4; off; off >>= 1) s += __shfl_xor_sync(0xFFFFFFFFu, s, off);
        if (t == 0) red[0] = rsqrtf(s * (1.0f / ND) + 1e-6f);
    }
    __syncthreads();
    const float inv = red[0];
    float4 gv = ((const float4*)g)[t];
    float4 ov;
    ov.x = v.x * inv * gv.x;
    ov.y = v.y * inv * gv.y;
    ov.z = v.z * inv * gv.z;
    ov.w = v.w * inv * gv.w;
    ((float4*)(o + base))[t] = ov;
}

// ---------------------------------------------------------------------------
// Generic GEMM  C = A[M,K] @ B[K,N]   (128x128 tile, BK=8, 8x8/thread, 256 thr)
// EPI: 0 plain  1 +residual  2 relu  3 head-layout [(b*H+h)*Lseq + l]*64 + hd
// M, N multiples of 128; K multiple of 8 (all true for this problem).
// ---------------------------------------------------------------------------
template<int EPI>
__global__ __launch_bounds__(256) void gemm128(
    const float* __restrict__ A, const float* __restrict__ B, float* __restrict__ C,
    int M, int N, int K, const float* __restrict__ resid, int Lseq)
{
    __shared__ float As[8][132];
    __shared__ float Bs[8][132];
    const int bm = blockIdx.y * 128;
    const int bn = blockIdx.x * 128;
    const int tid = threadIdx.x;
    const int arow = tid >> 1, acol = (tid & 1) * 4;
    const int brow = tid >> 5, bcol = (tid & 31) * 4;
    const int tc = tid & 15, tr = tid >> 4;
    const int tm0 = tr * 8, tn0 = tc * 8;

    const float* Ap = A + (size_t)(bm + arow) * K + acol;
    const float* Bp = B + (size_t)brow * N + bn + bcol;

    float acc[8][8];
    #pragma unroll
    for (int i = 0; i < 8; i++)
        #pragma unroll
        for (int j = 0; j < 8; j++) acc[i][j] = 0.0f;

    for (int k0 = 0; k0 < K; k0 += 8) {
        float4 av = *(const float4*)Ap;
        float4 bv = *(const float4*)Bp;
        As[acol + 0][arow] = av.x; As[acol + 1][arow] = av.y;
        As[acol + 2][arow] = av.z; As[acol + 3][arow] = av.w;
        *(float4*)(&Bs[brow][bcol]) = bv;
        __syncthreads();
        #pragma unroll
        for (int kk = 0; kk < 8; kk++) {
            float ar[8], br[8];
            *(float4*)(ar)     = *(const float4*)(&As[kk][tm0]);
            *(float4*)(ar + 4) = *(const float4*)(&As[kk][tm0 + 4]);
            *(float4*)(br)     = *(const float4*)(&Bs[kk][tn0]);
            *(float4*)(br + 4) = *(const float4*)(&Bs[kk][tn0 + 4]);
            #pragma unroll
            for (int i = 0; i < 8; i++)
                #pragma unroll
                for (int j = 0; j < 8; j++)
                    acc[i][j] += ar[i] * br[j];
        }
        __syncthreads();
        Ap += 8;
        Bp += (size_t)8 * N;
    }

    if (EPI == 3) {
        #pragma unroll
        for (int i = 0; i < 8; i++) {
            int m = bm + tm0 + i;
            int b = m / Lseq, l = m - b * Lseq;
            #pragma unroll
            for (int j = 0; j < 8; j++) {
                int n = bn + tn0 + j;
                int h = n >> 6, hd = n & 63;
                C[(((size_t)(b * NH + h)) * Lseq + l) * NHD + hd] = acc[i][j];
            }
        }
    } else {
        #pragma unroll
        for (int i = 0; i < 8; i++) {
            size_t base = (size_t)(bm + tm0 + i) * N + bn + tn0;
            #pragma unroll
            for (int j = 0; j < 8; j++) {
                float v = acc[i][j];
                if (EPI == 1) v += resid[base + j];
                if (EPI == 2) v = fmaxf(v, 0.0f);
                C[base + j] = v;
            }
        }
    }
}

// ---------------------------------------------------------------------------
// Batched scores: S[z,q,k] = (Q[z,q,:].K[z,k,:]) * 0.125 + bias[h,q,k]
// z = b*H+h. 128x128 tile, K-dim = 64 (BK=16), 8x8/thread.
// biasHeadElems = 0 -> same bias for all heads (causal mask [LT,LT]).
// ---------------------------------------------------------------------------
__global__ __launch_bounds__(256) void scores_kernel(
    const float* __restrict__ Q, const float* __restrict__ Kt, float* __restrict__ S,
    const float* __restrict__ bias, int biasHeadElems, int Lq, int Lk)
{
    __shared__ float Qs[16][132];
    __shared__ float Ks[16][132];
    const int z = blockIdx.z;
    const int h = z & (NH - 1);
    const float* Qb = Q  + (size_t)z * Lq * NHD;
    const float* Kb = Kt + (size_t)z * Lk * NHD;
    float* Sb = S + (size_t)z * Lq * Lk;
    const float* bb = bias + (size_t)h * biasHeadElems;

    const int bm = blockIdx.y * 128, bn = blockIdx.x * 128;
    const int tid = threadIdx.x;
    const int tc = tid & 15, tr = tid >> 4;
    const int tm0 = tr * 8, tn0 = tc * 8;

    float acc[8][8];
    #pragma unroll
    for (int i = 0; i < 8; i++)
        #pragma unroll
        for (int j = 0; j < 8; j++) acc[i][j] = 0.0f;

    for (int k0 = 0; k0 < NHD; k0 += 16) {
        #pragma unroll
        for (int u = 0; u < 2; u++) {
            int slot = tid + 256 * u;
            int row = slot >> 2;
            int k4 = (slot & 3) * 4;
            float4 qv = *(const float4*)(Qb + (size_t)(bm + row) * NHD + k0 + k4);
            Qs[k4 + 0][row] = qv.x; Qs[k4 + 1][row] = qv.y;
            Qs[k4 + 2][row] = qv.z; Qs[k4 + 3][row] = qv.w;
            float4 kv = *(const float4*)(Kb + (size_t)(bn + row) * NHD + k0 + k4);
            Ks[k4 + 0][row] = kv.x; Ks[k4 + 1][row] = kv.y;
            Ks[k4 + 2][row] = kv.z; Ks[k4 + 3][row] = kv.w;
        }
        __syncthreads();
        #pragma unroll
        for (int kk = 0; kk < 16; kk++) {
            float ar[8], br[8];
            *(float4*)(ar)     = *(const float4*)(&Qs[kk][tm0]);
            *(float4*)(ar + 4) = *(const float4*)(&Qs[kk][tm0 + 4]);
            *(float4*)(br)     = *(const float4*)(&Ks[kk][tn0]);
            *(float4*)(br + 4) = *(const float4*)(&Ks[kk][tn0 + 4]);
            #pragma unroll
            for (int i = 0; i < 8; i++)
                #pragma unroll
                for (int j = 0; j < 8; j++)
                    acc[i][j] += ar[i] * br[j];
        }
        __syncthreads();
    }

    #pragma unroll
    for (int i = 0; i < 8; i++) {
        int q = bm + tm0 + i;
        size_t rb = (size_t)q * Lk + bn + tn0;
        #pragma unroll
        for (int j = 0; j < 8; j++) {
            Sb[rb + j] = acc[i][j] * 0.125f + bb[rb + j];
        }
    }
}

// ---------------------------------------------------------------------------
// Row softmax over length 1024, in place. One block per row, 256 threads.
// ---------------------------------------------------------------------------
__global__ __launch_bounds__(256) void softmax_kernel(float* __restrict__ S)
{
    __shared__ float red[8];
    const size_t base = (size_t)blockIdx.x * NL;
    const int t = threadIdx.x;
    float4* Sv = (float4*)(S + base);
    float4 v = Sv[t];

    float m = fmaxf(fmaxf(v.x, v.y), fmaxf(v.z, v.w));
    #pragma unroll
    for (int off = 16; off; off >>= 1) m = fmaxf(m, __shfl_xor_sync(0xFFFFFFFFu, m, off));
    if ((t & 31) == 0) red[t >> 5] = m;
    __syncthreads();
    float rm = red[0];
    #pragma unroll
    for (int w = 1; w < 8; w++) rm = fmaxf(rm, red[w]);

    v.x = expf(v.x - rm); v.y = expf(v.y - rm);
    v.z = expf(v.z - rm); v.w = expf(v.w - rm);
    float s = v.x + v.y + v.z + v.w;
    #pragma unroll
    for (int off = 16; off; off >>= 1) s += __shfl_xor_sync(0xFFFFFFFFu, s, off);
    __syncthreads();
    if ((t & 31) == 0) red[t >> 5] = s;
    __syncthreads();
    float rs = red[0];
    #pragma unroll
    for (int w = 1; w < 8; w++) rs += red[w];
    float inv = 1.0f / rs;
    v.x *= inv; v.y *= inv; v.z *= inv; v.w *= inv;
    Sv[t] = v;
}

// ---------------------------------------------------------------------------
// Batched PV: O[b,q, h*64+n] = sum_k P[z,q,k] * V[z,k,n]   (z=b*H+h)
// 64x64 tile, BK=16, 4x4/thread, 256 threads. Writes [B,L,D] layout.
// ---------------------------------------------------------------------------
__global__ __launch_bounds__(256) void pv_kernel(
    const float* __restrict__ P, const float* __restrict__ V, float* __restrict__ O,
    int Lq, int Lk)
{
    __shared__ float Ps[16][68];
    __shared__ float Vs[16][68];
    const int z = blockIdx.z;
    const int b = z >> 4, h = z & 15;
    const float* Pb = P + (size_t)z * Lq * Lk;
    const float* Vb = V + (size_t)z * Lk * NHD;
    const int bm = blockIdx.y * 64;
    const int tid = threadIdx.x;
    const int tc = tid & 15, tr = tid >> 4;
    const int tm0 = tr * 4, tn0 = tc * 4;
    const int prow = tid >> 2, pk4 = (tid & 3) * 4;
    const int vrow = tid >> 4, vcol = (tid & 15) * 4;

    float acc[4][4];
    #pragma unroll
    for (int i = 0; i < 4; i++)
        #pragma unroll
        for (int j = 0; j < 4; j++) acc[i][j] = 0.0f;

    for (int k0 = 0; k0 < Lk; k0 += 16) {
        float4 pv4 = *(const float4*)(Pb + (size_t)(bm + prow) * Lk + k0 + pk4);
        Ps[pk4 + 0][prow] = pv4.x; Ps[pk4 + 1][prow] = pv4.y;
        Ps[pk4 + 2][prow] = pv4.z; Ps[pk4 + 3][prow] = pv4.w;
        float4 vv = *(const float4*)(Vb + (size_t)(k0 + vrow) * NHD + vcol);
        *(float4*)(&Vs[vrow][vcol]) = vv;
        __syncthreads();
        #pragma unroll
        for (int kk = 0; kk < 16; kk++) {
            float ar[4], br[4];
            *(float4*)ar = *(const float4*)(&Ps[kk][tm0]);
            *(float4*)br = *(const float4*)(&Vs[kk][tn0]);
            #pragma unroll
            for (int i = 0; i < 4; i++)
                #pragma unroll
                for (int j = 0; j < 4; j++)
                    acc[i][j] += ar[i] * br[j];
        }
        __syncthreads();
    }

    #pragma unroll
    for (int i = 0; i < 4; i++) {
        int q = bm + tm0 + i;
        size_t ob = ((size_t)(b * NL + q)) * ND + h * NHD + tn0;
        #pragma unroll
        for (int j = 0; j < 4; j++) O[ob + j] = acc[i][j];
    }
}

// ---------------------------------------------------------------------------
// Host driver
// ---------------------------------------------------------------------------
extern "C" void kernel_launch(void* const* d_in, const int* in_sizes, int n_in,
                              void* d_out, int out_size)
{
    const float* x    = (const float*)d_in[0];
    const float* mem  = (const float*)d_in[1];
    const float* pe   = (const float*)d_in[2];
    const float* cm   = (const float*)d_in[3];
    const float* ga_sa= (const float*)d_in[4];
    const float* wq_s = (const float*)d_in[5];
    const float* wk_s = (const float*)d_in[6];
    const float* wv_s = (const float*)d_in[7];
    const float* wo_s = (const float*)d_in[8];
    const float* ga_ca= (const float*)d_in[9];
    const float* wq_c = (const float*)d_in[10];
    const float* wk_c = (const float*)d_in[11];
    const float* wv_c = (const float*)d_in[12];
    const float* wo_c = (const float*)d_in[13];
    const float* ga_m = (const float*)d_in[14];
    const float* w1   = (const float*)d_in[15];
    const float* w2   = (const float*)d_in[16];
    float* out = (float*)d_out;

    // scratch pointers
    float *pH, *pQ, *pO, *pX1, *pX2, *pS, *pT, *pKV;
    cudaGetSymbolAddress((void**)&pH,  g_h);
    cudaGetSymbolAddress((void**)&pQ,  g_q);
    cudaGetSymbolAddress((void**)&pO,  g_o);
    cudaGetSymbolAddress((void**)&pX1, g_x1);
    cudaGetSymbolAddress((void**)&pX2, g_x2);
    cudaGetSymbolAddress((void**)&pS,  g_s);
    cudaGetSymbolAddress((void**)&pT,  g_t);
    cudaGetSymbolAddress((void**)&pKV, g_kv_full);

    // K/V output destinations (reference leaf order: mlp_x, k_s, v_s, k_c, v_c)
    float *kS, *vS, *kC, *vC;
    if ((size_t)out_size >= 5 * SEG) {
        kS = out + SEG; vS = out + 2 * SEG; kC = out + 3 * SEG; vC = out + 4 * SEG;
    } else {
        kS = pKV; vS = pKV + SEG; kC = pKV + 2 * SEG; vC = pKV + 3 * SEG;
    }

    const dim3 gProj(ND / 128, NROWS / 128);        // (8, 32)
    const dim3 gFFN1(NF / 128, NROWS / 128);        // (32, 32)
    const dim3 gScore(NL / 128, NL / 128, NB * NH); // (8, 8, 64)
    const dim3 gPV(1, NL / 64, NB * NH);            // (1, 16, 64)

    // ---- self attention ----
    rmsnorm_kernel<<<NROWS, 256>>>(x, ga_sa, pH);
    gemm128<3><<<gProj, 256>>>(pH, wq_s, pQ, NROWS, ND, ND, nullptr, NL);
    gemm128<3><<<gProj, 256>>>(pH, wk_s, kS, NROWS, ND, ND, nullptr, NL);
    gemm128<3><<<gProj, 256>>>(pH, wv_s, vS, NROWS, ND, ND, nullptr, NL);
    scores_kernel<<<gScore, 256>>>(pQ, kS, pS, cm, 0, NL, NL);
    softmax_kernel<<<NB * NH * NL, 256>>>(pS);
    pv_kernel<<<gPV, 256>>>(pS, vS, pO, NL, NL);
    gemm128<1><<<gProj, 256>>>(pO, wo_s, pX1, NROWS, ND, ND, x, 0);

    // ---- cross attention (q from normed attn_x; k,v from raw memory) ----
    rmsnorm_kernel<<<NROWS, 256>>>(pX1, ga_ca, pH);
    gemm128<3><<<gProj, 256>>>(pH,  wq_c, pQ, NROWS, ND, ND, nullptr, NL);
    gemm128<3><<<gProj, 256>>>(mem, wk_c, kC, NROWS, ND, ND, nullptr, NL);
    gemm128<3><<<gProj, 256>>>(mem, wv_c, vC, NROWS, ND, ND, nullptr, NL);
    scores_kernel<<<gScore, 256>>>(pQ, kC, pS, pe, NL * NL, NL, NL);
    softmax_kernel<<<NB * NH * NL, 256>>>(pS);
    pv_kernel<<<gPV, 256>>>(pS, vC, pO, NL, NL);
    gemm128<1><<<gProj, 256>>>(pO, wo_c, pX2, NROWS, ND, ND, pX1, 0);

    // ---- FFN ----
    rmsnorm_kernel<<<NROWS, 256>>>(pX2, ga_m, pH);
    gemm128<2><<<gFFN1, 256>>>(pH, w1, pT, NROWS, NF, ND, nullptr, 0);
    gemm128<1><<<gProj, 256>>>(pT, w2, out, NROWS, ND, NF, pX2, 0);
}

// round 5
// speedup vs baseline: 2.0446x; 2.0446x over previous
#include <cuda_runtime.h>
#include <cstdint>

// ---------------------------------------------------------------------------
// Decode layer: B=4, LT=LS=1024, D=1024, H=16, HD=64, F=4096
// Output: [mlp_x | k_s | v_s | k_c | v_c], each 4*1024*1024 fp32
// Round 3: all GEMMs on tensor pipe via mma.sync tf32 (rna-converted).
// ---------------------------------------------------------------------------

#define NB 4
#define NL 1024
#define ND 1024
#define NH 16
#define NHD 64
#define NF 4096
#define NROWS (NB * NL)                  // 4096
#define SEG   ((size_t)NB * NL * ND)     // 4,194,304

// ---------------- scratch (device globals) ---------------------------------
__device__ float g_h [NROWS * ND];
__device__ float g_q [(size_t)NB * NH * NL * NHD];
__device__ float g_o [NROWS * ND];
__device__ float g_x1[NROWS * ND];
__device__ float g_x2[NROWS * ND];
__device__ float g_s [(size_t)NB * NH * NL * NL];   // 256 MB scores
__device__ float g_t [(size_t)NROWS * NF];
__device__ float g_kv_full[4 * SEG];                // fallback only

// ---------------- tf32 helpers ---------------------------------------------
__device__ __forceinline__ uint32_t f2t(float f) {
    uint32_t r;
    asm("cvt.rna.tf32.f32 %0, %1;" : "=r"(r) : "f"(f));
    return r;
}

__device__ __forceinline__ void mma8(float* c, const uint32_t* a, const uint32_t* b) {
    asm volatile(
        "mma.sync.aligned.m16n8k8.row.col.f32.tf32.tf32.f32 "
        "{%0,%1,%2,%3}, {%4,%5,%6,%7}, {%8,%9}, {%0,%1,%2,%3};\n"
        : "+f"(c[0]), "+f"(c[1]), "+f"(c[2]), "+f"(c[3])
        : "r"(a[0]), "r"(a[1]), "r"(a[2]), "r"(a[3]), "r"(b[0]), "r"(b[1]));
}

// ---------------------------------------------------------------------------
// RMSNorm (unchanged)
// ---------------------------------------------------------------------------
__global__ __launch_bounds__(256) void rmsnorm_kernel(
    const float* __restrict__ x, const float* __restrict__ g, float* __restrict__ o)
{
    __shared__ float red[8];
    const size_t base = (size_t)blockIdx.x * ND;
    const int t = threadIdx.x;
    float4 v = ((const float4*)(x + base))[t];
    float ss = v.x*v.x + v.y*v.y + v.z*v.z + v.w*v.w;
    #pragma unroll
    for (int off = 16; off; off >>= 1) ss += __shfl_xor_sync(0xFFFFFFFFu, ss, off);
    if ((t & 31) == 0) red[t >> 5] = ss;
    __syncthreads();
    if (t < 32) {
        float s = (t < 8) ? red[t] : 0.0f;
        #pragma unroll
        for (int off = 4; off; off >>= 1) s += __shfl_xor_sync(0xFFFFFFFFu, s, off);
        if (t == 0) red[0] = rsqrtf(s * (1.0f / ND) + 1e-6f);
    }
    __syncthreads();
    const float inv = red[0];
    float4 gv = ((const float4*)g)[t];
    float4 ov;
    ov.x = v.x * inv * gv.x; ov.y = v.y * inv * gv.y;
    ov.z = v.z * inv * gv.z; ov.w = v.w * inv * gv.w;
    ((float4*)(o + base))[t] = ov;
}

// ---------------------------------------------------------------------------
// tf32 tensor-core GEMM  C = A[M,K] @ B[K,N]
// 128x128x32 tiles, double-buffered smem, 8 warps (2m x 4n), warp tile 64x32.
// EPI: 1 +residual   2 relu   3 head-layout write
// smem: As[2][128][36]  Bs[2][32][136]  (71680 B dynamic)
// ---------------------------------------------------------------------------
#define MM_SMEM ((2*128*36 + 2*32*136) * 4)

template<int EPI>
__global__ __launch_bounds__(256) void mm_tf32(
    const float* __restrict__ A, const float* __restrict__ B, float* __restrict__ C,
    int M, int N, int K, const float* __restrict__ resid, int Lseq)
{
    extern __shared__ uint32_t sm[];
    uint32_t* As = sm;                // [2][128][36]
    uint32_t* Bs = sm + 2*128*36;     // [2][32][136]

    const int tid  = threadIdx.x;
    const int lane = tid & 31;
    const int warp = tid >> 5;
    const int wm = warp & 1, wn = warp >> 1;   // 2 x 4
    const int g = lane >> 2, tg = lane & 3;
    const int bm = blockIdx.y * 128, bn = blockIdx.x * 128;

    const int arow = tid >> 1, acol = (tid & 1) * 16;   // A: 1 row, 16 cols
    const int brow = tid >> 3, bcol = (tid & 7) * 16;   // B: 1 row, 16 cols

    const float* Ag = A + (size_t)(bm + arow) * K + acol;
    const float* Bg = B + (size_t)brow * N + bn + bcol;

    float ra[16], rb[16];
    #pragma unroll
    for (int i = 0; i < 4; i++) *(float4*)(ra + 4*i) = *(const float4*)(Ag + 4*i);
    #pragma unroll
    for (int i = 0; i < 4; i++) *(float4*)(rb + 4*i) = *(const float4*)(Bg + 4*i);

    {   // STS stage 0
        uint32_t* as = As + arow*36 + acol;
        #pragma unroll
        for (int i = 0; i < 16; i++) as[i] = f2t(ra[i]);
        uint32_t* bs = Bs + brow*136 + bcol;
        #pragma unroll
        for (int i = 0; i < 16; i++) bs[i] = f2t(rb[i]);
    }
    __syncthreads();

    float acc[4][4][4];
    #pragma unroll
    for (int mt = 0; mt < 4; mt++)
        #pragma unroll
        for (int nt = 0; nt < 4; nt++)
            #pragma unroll
            for (int i = 0; i < 4; i++) acc[mt][nt][i] = 0.0f;

    const int T = K >> 5;
    for (int t = 0; t < T; t++) {
        if (t + 1 < T) {
            const float* Ag2 = Ag + (t + 1) * 32;
            const float* Bg2 = Bg + (size_t)(t + 1) * 32 * N;
            #pragma unroll
            for (int i = 0; i < 4; i++) *(float4*)(ra + 4*i) = *(const float4*)(Ag2 + 4*i);
            #pragma unroll
            for (int i = 0; i < 4; i++) *(float4*)(rb + 4*i) = *(const float4*)(Bg2 + 4*i);
        }
        const uint32_t* as = As + (t & 1) * 128 * 36;
        const uint32_t* bs = Bs + (t & 1) * 32 * 136;
        #pragma unroll
        for (int ks = 0; ks < 4; ks++) {
            uint32_t af[4][4], bf[4][2];
            #pragma unroll
            for (int mt = 0; mt < 4; mt++) {
                const uint32_t* ap = as + (wm*64 + mt*16 + g) * 36 + ks*8 + tg;
                af[mt][0] = ap[0];
                af[mt][1] = ap[8*36];
                af[mt][2] = ap[4];
                af[mt][3] = ap[8*36 + 4];
            }
            #pragma unroll
            for (int nt = 0; nt < 4; nt++) {
                const uint32_t* bp = bs + (ks*8 + tg) * 136 + wn*32 + nt*8 + g;
                bf[nt][0] = bp[0];
                bf[nt][1] = bp[4*136];
            }
            #pragma unroll
            for (int mt = 0; mt < 4; mt++)
                #pragma unroll
                for (int nt = 0; nt < 4; nt++)
                    mma8(acc[mt][nt], af[mt], bf[nt]);
        }
        if (t + 1 < T) {
            uint32_t* asw = As + ((t + 1) & 1) * 128 * 36 + arow*36 + acol;
            #pragma unroll
            for (int i = 0; i < 16; i++) asw[i] = f2t(ra[i]);
            uint32_t* bsw = Bs + ((t + 1) & 1) * 32 * 136 + brow*136 + bcol;
            #pragma unroll
            for (int i = 0; i < 16; i++) bsw[i] = f2t(rb[i]);
        }
        __syncthreads();
    }

    // epilogue: acc[mt][nt] = {(r0,c0),(r0,c1),(r1,c0),(r1,c1)} r1=r0+8
    #pragma unroll
    for (int mt = 0; mt < 4; mt++) {
        const int r0 = bm + wm*64 + mt*16 + g;
        #pragma unroll
        for (int half = 0; half < 2; half++) {
            const int row = r0 + half * 8;
            #pragma unroll
            for (int nt = 0; nt < 4; nt++) {
                const int col = bn + wn*32 + nt*8 + tg*2;
                float v0 = acc[mt][nt][half*2 + 0];
                float v1 = acc[mt][nt][half*2 + 1];
                if (EPI == 3) {
                    const int b = row / Lseq, l = row - b * Lseq;
                    const int h = col >> 6, hd = col & 63;
                    float2* dst = (float2*)(C + (((size_t)(b*NH + h))*Lseq + l)*NHD + hd);
                    *dst = make_float2(v0, v1);
                } else {
                    const size_t base = (size_t)row * N + col;
                    if (EPI == 1) {
                        float2 rv = *(const float2*)(resid + base);
                        v0 += rv.x; v1 += rv.y;
                    }
                    if (EPI == 2) { v0 = fmaxf(v0, 0.0f); v1 = fmaxf(v1, 0.0f); }
                    *(float2*)(C + base) = make_float2(v0, v1);
                }
            }
        }
    }
}

// ---------------------------------------------------------------------------
// Batched scores (tf32): S[z,q,k] = (Q[z,q,:].K[z,k,:])*0.125 + bias
// 128x128 tile, K=64 single shot. smem Qs/Ks [128][68] (69632 B dynamic)
// ---------------------------------------------------------------------------
#define SC_SMEM (2*128*68*4)

__global__ __launch_bounds__(256) void scores_tf32(
    const float* __restrict__ Q, const float* __restrict__ Kt, float* __restrict__ S,
    const float* __restrict__ bias, int biasHeadElems)
{
    extern __shared__ uint32_t sm[];
    uint32_t* Qs = sm;              // [128][68]
    uint32_t* Ks = sm + 128*68;     // [128][68]  (row = key index n, col = k)

    const int tid  = threadIdx.x;
    const int lane = tid & 31, warp = tid >> 5;
    const int wm = warp & 1, wn = warp >> 1;
    const int g = lane >> 2, tg = lane & 3;
    const int z = blockIdx.z, h = z & (NH - 1);
    const float* Qb = Q  + (size_t)z * NL * NHD;
    const float* Kb = Kt + (size_t)z * NL * NHD;
    float* Sb = S + (size_t)z * NL * NL;
    const float* bb = bias + (size_t)h * biasHeadElems;
    const int bm = blockIdx.y * 128, bn = blockIdx.x * 128;

    const int lrow = tid >> 1, lcol = (tid & 1) * 32;
    {
        const float* qp = Qb + (size_t)(bm + lrow) * NHD + lcol;
        const float* kp = Kb + (size_t)(bn + lrow) * NHD + lcol;
        uint32_t* qs = Qs + lrow*68 + lcol;
        uint32_t* ks = Ks + lrow*68 + lcol;
        #pragma unroll
        for (int i = 0; i < 8; i++) {
            float4 v = *(const float4*)(qp + 4*i);
            qs[4*i+0]=f2t(v.x); qs[4*i+1]=f2t(v.y); qs[4*i+2]=f2t(v.z); qs[4*i+3]=f2t(v.w);
            float4 w = *(const float4*)(kp + 4*i);
            ks[4*i+0]=f2t(w.x); ks[4*i+1]=f2t(w.y); ks[4*i+2]=f2t(w.z); ks[4*i+3]=f2t(w.w);
        }
    }
    __syncthreads();

    float acc[4][4][4];
    #pragma unroll
    for (int mt = 0; mt < 4; mt++)
        #pragma unroll
        for (int nt = 0; nt < 4; nt++)
            #pragma unroll
            for (int i = 0; i < 4; i++) acc[mt][nt][i] = 0.0f;

    #pragma unroll
    for (int ks_ = 0; ks_ < 8; ks_++) {
        uint32_t af[4][4], bf[4][2];
        #pragma unroll
        for (int mt = 0; mt < 4; mt++) {
            const uint32_t* ap = Qs + (wm*64 + mt*16 + g) * 68 + ks_*8 + tg;
            af[mt][0] = ap[0]; af[mt][1] = ap[8*68]; af[mt][2] = ap[4]; af[mt][3] = ap[8*68+4];
        }
        #pragma unroll
        for (int nt = 0; nt < 4; nt++) {
            const uint32_t* bp = Ks + (wn*32 + nt*8 + g) * 68 + ks_*8 + tg;
            bf[nt][0] = bp[0]; bf[nt][1] = bp[4];
        }
        #pragma unroll
        for (int mt = 0; mt < 4; mt++)
            #pragma unroll
            for (int nt = 0; nt < 4; nt++)
                mma8(acc[mt][nt], af[mt], bf[nt]);
    }

    #pragma unroll
    for (int mt = 0; mt < 4; mt++) {
        const int r0 = bm + wm*64 + mt*16 + g;
        #pragma unroll
        for (int half = 0; half < 2; half++) {
            const int row = r0 + half * 8;
            #pragma unroll
            for (int nt = 0; nt < 4; nt++) {
                const int col = bn + wn*32 + nt*8 + tg*2;
                const size_t base = (size_t)row * NL + col;
                float2 bv = *(const float2*)(bb + base);
                float v0 = acc[mt][nt][half*2+0] * 0.125f + bv.x;
                float v1 = acc[mt][nt][half*2+1] * 0.125f + bv.y;
                *(float2*)(Sb + base) = make_float2(v0, v1);
            }
        }
    }
}

// ---------------------------------------------------------------------------
// Row softmax (unchanged)
// ---------------------------------------------------------------------------
__global__ __launch_bounds__(256) void softmax_kernel(float* __restrict__ S)
{
    __shared__ float red[8];
    const size_t base = (size_t)blockIdx.x * NL;
    const int t = threadIdx.x;
    float4* Sv = (float4*)(S + base);
    float4 v = Sv[t];

    float m = fmaxf(fmaxf(v.x, v.y), fmaxf(v.z, v.w));
    #pragma unroll
    for (int off = 16; off; off >>= 1) m = fmaxf(m, __shfl_xor_sync(0xFFFFFFFFu, m, off));
    if ((t & 31) == 0) red[t >> 5] = m;
    __syncthreads();
    float rm = red[0];
    #pragma unroll
    for (int w = 1; w < 8; w++) rm = fmaxf(rm, red[w]);

    v.x = expf(v.x - rm); v.y = expf(v.y - rm);
    v.z = expf(v.z - rm); v.w = expf(v.w - rm);
    float s = v.x + v.y + v.z + v.w;
    #pragma unroll
    for (int off = 16; off; off >>= 1) s += __shfl_xor_sync(0xFFFFFFFFu, s, off);
    __syncthreads();
    if ((t & 31) == 0) red[t >> 5] = s;
    __syncthreads();
    float rs = red[0];
    #pragma unroll
    for (int w = 1; w < 8; w++) rs += red[w];
    float inv = 1.0f / rs;
    v.x *= inv; v.y *= inv; v.z *= inv; v.w *= inv;
    Sv[t] = v;
}

// ---------------------------------------------------------------------------
// Batched PV (tf32): O[b,q,h*64+n] = sum_k P[z,q,k] V[z,k,n]
// 128x64x32 tiles, double buffered. 8 warps (4m x 2n), warp tile 32x32.
// smem: Ps[2][128][36], Vs[2][64][37]  (55808 B dynamic)
// ---------------------------------------------------------------------------
#define PV_SMEM ((2*128*36 + 2*64*37) * 4)

__global__ __launch_bounds__(256) void pv_tf32(
    const float* __restrict__ P, const float* __restrict__ V, float* __restrict__ O)
{
    extern __shared__ uint32_t sm[];
    uint32_t* Ps = sm;                // [2][128][36]
    uint32_t* Vs = sm + 2*128*36;     // [2][64][37]  (row = n, col = k)

    const int tid  = threadIdx.x;
    const int lane = tid & 31, warp = tid >> 5;
    const int wm = warp & 3, wn = warp >> 2;   // 4 x 2
    const int g = lane >> 2, tg = lane & 3;
    const int z = blockIdx.z, b = z >> 4, h = z & 15;
    const float* Pb = P + (size_t)z * NL * NL;
    const float* Vb = V + (size_t)z * NL * NHD;
    const int bm = blockIdx.y * 128;

    const int prow = tid >> 1, pcol = (tid & 1) * 16;
    const int vrow = tid >> 3, vcol = (tid & 7) * 8;

    const float* Pg = Pb + (size_t)(bm + prow) * NL + pcol;
    const float* Vg = Vb + (size_t)vrow * NHD + vcol;

    float rp[16], rv[8];
    #pragma unroll
    for (int i = 0; i < 4; i++) *(float4*)(rp + 4*i) = *(const float4*)(Pg + 4*i);
    #pragma unroll
    for (int i = 0; i < 2; i++) *(float4*)(rv + 4*i) = *(const float4*)(Vg + 4*i);

    {
        uint32_t* ps = Ps + prow*36 + pcol;
        #pragma unroll
        for (int i = 0; i < 16; i++) ps[i] = f2t(rp[i]);
        #pragma unroll
        for (int i = 0; i < 8; i++) Vs[(vcol + i)*37 + vrow] = f2t(rv[i]);
    }
    __syncthreads();

    float acc[2][4][4];
    #pragma unroll
    for (int mt = 0; mt < 2; mt++)
        #pragma unroll
        for (int nt = 0; nt < 4; nt++)
            #pragma unroll
            for (int i = 0; i < 4; i++) acc[mt][nt][i] = 0.0f;

    const int T = NL >> 5;   // 32
    for (int t = 0; t < T; t++) {
        if (t + 1 < T) {
            const float* Pg2 = Pg + (t + 1) * 32;
            const float* Vg2 = Vg + (size_t)(t + 1) * 32 * NHD;
            #pragma unroll
            for (int i = 0; i < 4; i++) *(float4*)(rp + 4*i) = *(const float4*)(Pg2 + 4*i);
            #pragma unroll
            for (int i = 0; i < 2; i++) *(float4*)(rv + 4*i) = *(const float4*)(Vg2 + 4*i);
        }
        const uint32_t* ps = Ps + (t & 1) * 128 * 36;
        const uint32_t* vs = Vs + (t & 1) * 64 * 37;
        #pragma unroll
        for (int ks = 0; ks < 4; ks++) {
            uint32_t af[2][4], bf[4][2];
            #pragma unroll
            for (int mt = 0; mt < 2; mt++) {
                const uint32_t* ap = ps + (wm*32 + mt*16 + g) * 36 + ks*8 + tg;
                af[mt][0] = ap[0]; af[mt][1] = ap[8*36]; af[mt][2] = ap[4]; af[mt][3] = ap[8*36+4];
            }
            #pragma unroll
            for (int nt = 0; nt < 4; nt++) {
                const uint32_t* bp = vs + (wn*32 + nt*8 + g) * 37 + ks*8 + tg;
                bf[nt][0] = bp[0]; bf[nt][1] = bp[4];
            }
            #pragma unroll
            for (int mt = 0; mt < 2; mt++)
                #pragma unroll
                for (int nt = 0; nt < 4; nt++)
                    mma8(acc[mt][nt], af[mt], bf[nt]);
        }
        if (t + 1 < T) {
            uint32_t* psw = Ps + ((t + 1) & 1) * 128 * 36 + prow*36 + pcol;
            #pragma unroll
            for (int i = 0; i < 16; i++) psw[i] = f2t(rp[i]);
            uint32_t* vsw = Vs + ((t + 1) & 1) * 64 * 37;
            #pragma unroll
            for (int i = 0; i < 8; i++) vsw[(vcol + i)*37 + vrow] = f2t(rv[i]);
        }
        __syncthreads();
    }

    #pragma unroll
    for (int mt = 0; mt < 2; mt++) {
        const int q0 = bm + wm*32 + mt*16 + g;
        #pragma unroll
        for (int half = 0; half < 2; half++) {
            const int q = q0 + half * 8;
            #pragma unroll
            for (int nt = 0; nt < 4; nt++) {
                const int n = wn*32 + nt*8 + tg*2;
                float2* dst = (float2*)(O + ((size_t)(b*NL + q))*ND + h*NHD + n);
                *dst = make_float2(acc[mt][nt][half*2+0], acc[mt][nt][half*2+1]);
            }
        }
    }
}

// ---------------------------------------------------------------------------
// Host driver
// ---------------------------------------------------------------------------
extern "C" void kernel_launch(void* const* d_in, const int* in_sizes, int n_in,
                              void* d_out, int out_size)
{
    const float* x    = (const float*)d_in[0];
    const float* mem  = (const float*)d_in[1];
    const float* pe   = (const float*)d_in[2];
    const float* cm   = (const float*)d_in[3];
    const float* ga_sa= (const float*)d_in[4];
    const float* wq_s = (const float*)d_in[5];
    const float* wk_s = (const float*)d_in[6];
    const float* wv_s = (const float*)d_in[7];
    const float* wo_s = (const float*)d_in[8];
    const float* ga_ca= (const float*)d_in[9];
    const float* wq_c = (const float*)d_in[10];
    const float* wk_c = (const float*)d_in[11];
    const float* wv_c = (const float*)d_in[12];
    const float* wo_c = (const float*)d_in[13];
    const float* ga_m = (const float*)d_in[14];
    const float* w1   = (const float*)d_in[15];
    const float* w2   = (const float*)d_in[16];
    float* out = (float*)d_out;

    static bool attr_done = false;
    if (!attr_done) {
        cudaFuncSetAttribute(mm_tf32<1>, cudaFuncAttributeMaxDynamicSharedMemorySize, MM_SMEM);
        cudaFuncSetAttribute(mm_tf32<2>, cudaFuncAttributeMaxDynamicSharedMemorySize, MM_SMEM);
        cudaFuncSetAttribute(mm_tf32<3>, cudaFuncAttributeMaxDynamicSharedMemorySize, MM_SMEM);
        cudaFuncSetAttribute(scores_tf32, cudaFuncAttributeMaxDynamicSharedMemorySize, SC_SMEM);
        cudaFuncSetAttribute(pv_tf32,     cudaFuncAttributeMaxDynamicSharedMemorySize, PV_SMEM);
        attr_done = true;
    }

    float *pH, *pQ, *pO, *pX1, *pX2, *pS, *pT, *pKV;
    cudaGetSymbolAddress((void**)&pH,  g_h);
    cudaGetSymbolAddress((void**)&pQ,  g_q);
    cudaGetSymbolAddress((void**)&pO,  g_o);
    cudaGetSymbolAddress((void**)&pX1, g_x1);
    cudaGetSymbolAddress((void**)&pX2, g_x2);
    cudaGetSymbolAddress((void**)&pS,  g_s);
    cudaGetSymbolAddress((void**)&pT,  g_t);
    cudaGetSymbolAddress((void**)&pKV, g_kv_full);

    float *kS, *vS, *kC, *vC;
    if ((size_t)out_size >= 5 * SEG) {
        kS = out + SEG; vS = out + 2*SEG; kC = out + 3*SEG; vC = out + 4*SEG;
    } else {
        kS = pKV; vS = pKV + SEG; kC = pKV + 2*SEG; vC = pKV + 3*SEG;
    }

    const dim3 gProj(ND / 128, NROWS / 128);         // (8, 32)
    const dim3 gFFN1(NF / 128, NROWS / 128);         // (32, 32)
    const dim3 gScore(NL / 128, NL / 128, NB * NH);  // (8, 8, 64)
    const dim3 gPV(1, NL / 128, NB * NH);            // (1, 8, 64)

    // ---- self attention ----
    rmsnorm_kernel<<<NROWS, 256>>>(x, ga_sa, pH);
    mm_tf32<3><<<gProj, 256, MM_SMEM>>>(pH, wq_s, pQ, NROWS, ND, ND, nullptr, NL);
    mm_tf32<3><<<gProj, 256, MM_SMEM>>>(pH, wk_s, kS, NROWS, ND, ND, nullptr, NL);
    mm_tf32<3><<<gProj, 256, MM_SMEM>>>(pH, wv_s, vS, NROWS, ND, ND, nullptr, NL);
    scores_tf32<<<gScore, 256, SC_SMEM>>>(pQ, kS, pS, cm, 0);
    softmax_kernel<<<NB * NH * NL, 256>>>(pS);
    pv_tf32<<<gPV, 256, PV_SMEM>>>(pS, vS, pO);
    mm_tf32<1><<<gProj, 256, MM_SMEM>>>(pO, wo_s, pX1, NROWS, ND, ND, x, 0);

    // ---- cross attention ----
    rmsnorm_kernel<<<NROWS, 256>>>(pX1, ga_ca, pH);
    mm_tf32<3><<<gProj, 256, MM_SMEM>>>(pH,  wq_c, pQ, NROWS, ND, ND, nullptr, NL);
    mm_tf32<3><<<gProj, 256, MM_SMEM>>>(mem, wk_c, kC, NROWS, ND, ND, nullptr, NL);
    mm_tf32<3><<<gProj, 256, MM_SMEM>>>(mem, wv_c, vC, NROWS, ND, ND, nullptr, NL);
    scores_tf32<<<gScore, 256, SC_SMEM>>>(pQ, kC, pS, pe, NL * NL);
    softmax_kernel<<<NB * NH * NL, 256>>>(pS);
    pv_tf32<<<gPV, 256, PV_SMEM>>>(pS, vC, pO);
    mm_tf32<1><<<gProj, 256, MM_SMEM>>>(pO, wo_c, pX2, NROWS, ND, ND, pX1, 0);

    // ---- FFN ----
    rmsnorm_kernel<<<NROWS, 256>>>(pX2, ga_m, pH);
    mm_tf32<2><<<gFFN1, 256, MM_SMEM>>>(pH, w1, pT, NROWS, NF, ND, nullptr, 0);
    mm_tf32<1><<<gProj, 256, MM_SMEM>>>(pT, w2, out, NROWS, ND, NF, pX2, 0);
}